// round 13
// baseline (speedup 1.0000x reference)
#include <cuda_runtime.h>
#include <cstdint>
#include <math.h>

// Accurate libdevice log — used ONLY in the rare exact-fallback path so the
// argmax ordering is provably identical to the XLA reference.
extern "C" __device__ float __nv_logf(float);

// Rotation multipliers 2^r in __constant__: ptxas cannot constant-fold them
// (runtime-writable), so mul.wide.u32 stays IMAD.WIDE on the fma pipe. They
// load into uniform registers -> zero per-thread register cost.
__constant__ unsigned c_m13 = 1u << 13;
__constant__ unsigned c_m15 = 1u << 15;
__constant__ unsigned c_m17 = 1u << 17;
__constant__ unsigned c_m29 = 1u << 29;
__constant__ unsigned c_m24 = 1u << 24;

// 32x32 -> 64 widening multiply (single IMAD.WIDE.U32 in SASS)
__device__ __forceinline__ unsigned long long mulwide(unsigned a, unsigned m) {
    unsigned long long p;
    asm("mul.wide.u32 %0, %1, %2;" : "=l"(p) : "r"(a), "r"(m));
    return p;
}

// ---------------------------------------------------------------------------
// Compile-time Threefry-2x32 for split keys (partitionable fold-like split).
// ---------------------------------------------------------------------------
constexpr unsigned crotl(unsigned x, int r) { return (x << r) | (x >> (32 - r)); }
struct CKeys { unsigned a, b; };
constexpr CKeys ctf(unsigned k0, unsigned k1, unsigned x0, unsigned x1) {
    unsigned k2 = k0 ^ k1 ^ 0x1BD11BDAu;
    const int rotA[4] = {13, 15, 26, 6};
    const int rotB[4] = {17, 29, 16, 24};
    x0 += k0; x1 += k1;
    for (int i = 0; i < 4; i++) { x0 += x1; x1 = crotl(x1, rotA[i]); x1 ^= x0; }
    x0 += k1; x1 += k2 + 1u;
    for (int i = 0; i < 4; i++) { x0 += x1; x1 = crotl(x1, rotB[i]); x1 ^= x0; }
    x0 += k2; x1 += k0 + 2u;
    for (int i = 0; i < 4; i++) { x0 += x1; x1 = crotl(x1, rotA[i]); x1 ^= x0; }
    x0 += k0; x1 += k1 + 3u;
    for (int i = 0; i < 4; i++) { x0 += x1; x1 = crotl(x1, rotB[i]); x1 ^= x0; }
    x0 += k1; x1 += k2 + 4u;
    for (int i = 0; i < 4; i++) { x0 += x1; x1 = crotl(x1, rotA[i]); x1 ^= x0; }
    x0 += k2; x1 += k0 + 5u;
    return {x0, x1};
}
constexpr CKeys KCAT  = ctf(0u, 42u, 0u, 0u);   // k_cat
constexpr CKeys KBERN = ctf(0u, 42u, 0u, 1u);   // k_bern

// ---------------------------------------------------------------------------
// Device Threefry-2x32; partitionable 32-bit bits = lane0 ^ lane1, ctr (0, j).
// x1 must be ctr + k1 (pre-added by the caller). 12 of 20 rotations run as
// IMAD.WIDE (fma pipe) + one fused LOP3 ((lo|hi)^x0); 8 stay as SHF (alu) to
// keep the two pipes balanced.
// ---------------------------------------------------------------------------
__device__ __forceinline__ unsigned rotl(unsigned x, int r) {
    return __funnelshift_l(x, x, r);
}

__device__ __forceinline__ unsigned tf_bits32p(unsigned k0, unsigned k1, unsigned x1,
                                               unsigned m13, unsigned m15,
                                               unsigned m17, unsigned m29,
                                               unsigned m24) {
    const unsigned k2 = k0 ^ k1 ^ 0x1BD11BDAu;
    unsigned x0 = k0;
#define TFRS(r) { x0 += x1; x1 = rotl(x1, r); x1 ^= x0; }
#define TFRM(m) { x0 += x1; unsigned long long p = mulwide(x1, m); \
                  x1 = ((unsigned)p | (unsigned)(p >> 32)) ^ x0; }
    TFRM(m13) TFRM(m15) TFRS(26) TFRS(6)
    x0 += k1; x1 += k2 + 1u;
    TFRM(m17) TFRM(m29) TFRS(16) TFRM(m24)
    x0 += k2; x1 += k0 + 2u;
    TFRM(m13) TFRM(m15) TFRS(26) TFRS(6)
    x0 += k0; x1 += k1 + 3u;
    TFRM(m17) TFRM(m29) TFRS(16) TFRM(m24)
    x0 += k1; x1 += k2 + 4u;
    TFRM(m13) TFRM(m15) TFRS(26) TFRS(6)
#undef TFRS
#undef TFRM
    return (x0 + k2) ^ (x1 + k0 + 5u);
}

// JAX uniform [0,1): bit-identical to bitcast((bits>>9)|0x3f800000)-1
// ((bits>>9) < 2^23 => exact I2F; *2^-23 exact)
__device__ __forceinline__ float u01f(unsigned bits) {
    return (float)(bits >> 9) * 1.1920928955078125e-7f;   // 2^-23
}

#define TINY    1.17549435e-38f
#define L2E     1.44269504088896340736f   /* 1/ln2 */
#define L2EH    0.72134752044448170368f   /* 1/(2 ln2) */
#define D_SER   0.001953125f              /* d <= 2^-9: use series for -lg2(u) */
#define GAPTHR2 7.5e-4f                   /* s2-units; >=2x worst screen error */

// (value, index) max with exact second-max propagation; ties -> lower index
struct TopK { float v1; float v2; int i1; };
__device__ __forceinline__ TopK tk_merge(TopK a, TopK b) {
    TopK r;
    if (b.v1 > a.v1) { r.v1 = b.v1; r.i1 = b.i1; r.v2 = fmaxf(a.v1, b.v2); }
    else             { r.v1 = a.v1; r.i1 = a.i1; r.v2 = fmaxf(b.v1, a.v2); }
    return r;
}

// ---------------------------------------------------------------------------
// One thread per 8x8 window (proven shape, 64-thread blocks). Phase-split
// threefry, log2-domain branch-free scores, tournament top-2, rare exact
// fallback. u==0 slots need no guard: -lg2(0)=+inf => s=-inf, the slot loses
// on the cheap path exactly as it must in the reference (P(win) ~ e^-90).
// ---------------------------------------------------------------------------
__global__ __launch_bounds__(64)
void keypoint_sampler_kernel(const float* __restrict__ x, float* __restrict__ out) {
    const unsigned m13 = c_m13, m15 = c_m15, m17 = c_m17, m29 = c_m29, m24 = c_m24;

    const unsigned w = blockIdx.x * 64u + threadIdx.x;   // 0 .. 524287

    const unsigned b  = w >> 16;
    const unsigned hc = (w >> 8) & 255u;
    const unsigned wc = w & 255u;

    const float* base = x + ((size_t)b << 22) + (size_t)(hc * 8u) * 2048u + wc * 8u;

    // Bernoulli bits early (independent ILP across the whole mainloop)
    const unsigned bbits = tf_bits32p(KBERN.a, KBERN.b, w + KBERN.b,
                                      m13, m15, m17, m29, m24);

    TopK top; top.v1 = -3.4e38f; top.v2 = -3.4e38f; top.i1 = 0;
    float es0 = 0.f, es1 = 0.f, es2 = 0.f, es3 = 0.f;

    const unsigned cbase = w * 64u;

#pragma unroll 1
    for (int r = 0; r < 8; r++) {
        const float4 p0 = *(const float4*)(base + (size_t)r * 2048u);
        const float4 p1 = *(const float4*)(base + (size_t)r * 2048u + 4u);
        float v[8] = {p0.x, p0.y, p0.z, p0.w, p1.x, p1.y, p1.z, p1.w};

        const unsigned ckr = cbase + (unsigned)r * 8u + KCAT.b;  // ctr + k1

        // Phase 1: 8 independent threefry chains in flight
        unsigned g[8];
#pragma unroll
        for (int i = 0; i < 8; i++)
            g[i] = tf_bits32p(KCAT.a, KCAT.b, ckr + (unsigned)i,
                              m13, m15, m17, m29, m24);

        // Phase 2: 8 independent score pipelines, branch-free
        float s[8];
#pragma unroll
        for (int i = 0; i < 8; i++) {
            const float u = u01f(g[i]);
            const float d   = 1.0f - u;
            const float t2m = -__log2f(u);                    // MUFU path (+inf at u=0)
            const float t2f = d * fmaf(d, L2EH, L2E);         // series path
            const float t2  = (d < D_SER) ? t2f : t2m;
            const float p   = v[i] * L2E;
            s[i] = p - __log2f(t2);                           // score/ln2
            const float ev = exp2f(p);                        // == expf(v)
            if ((i & 3) == 0) es0 += ev;
            else if ((i & 3) == 1) es1 += ev;
            else if ((i & 3) == 2) es2 += ev;
            else es3 += ev;
        }

        // Tournament top-2 within the row (depth 3), ties -> lower index
        TopK t01, t23, t45, t67, ta, tb, row;
        t01.v1 = (s[1] > s[0]) ? s[1] : s[0];
        t01.i1 = (s[1] > s[0]) ? r*8+1 : r*8+0;
        t01.v2 = fminf(s[0], s[1]);
        t23.v1 = (s[3] > s[2]) ? s[3] : s[2];
        t23.i1 = (s[3] > s[2]) ? r*8+3 : r*8+2;
        t23.v2 = fminf(s[2], s[3]);
        t45.v1 = (s[5] > s[4]) ? s[5] : s[4];
        t45.i1 = (s[5] > s[4]) ? r*8+5 : r*8+4;
        t45.v2 = fminf(s[4], s[5]);
        t67.v1 = (s[7] > s[6]) ? s[7] : s[6];
        t67.i1 = (s[7] > s[6]) ? r*8+7 : r*8+6;
        t67.v2 = fminf(s[6], s[7]);
        ta  = tk_merge(t01, t23);
        tb  = tk_merge(t45, t67);
        row = tk_merge(ta, tb);
        top = tk_merge(top, row);
    }

    int bi = top.i1;

    // Ambiguous top-2 (P ~ 1e-3): redo window bitwise-exact.
    if (top.v1 - top.v2 < GAPTHR2) {
        float best = -3.4e38f; bi = 0;
#pragma unroll 1
        for (int r = 0; r < 8; r++) {
#pragma unroll 1
            for (int i = 0; i < 8; i++) {
                const unsigned gb = tf_bits32p(KCAT.a, KCAT.b,
                                    cbase + (unsigned)(r * 8 + i) + KCAT.b,
                                    m13, m15, m17, m29, m24);
                const float uu = fmaxf(u01f(gb), TINY);
                const float tt = -__nv_logf(uu);
                const float s = __ldg(base + (size_t)r * 2048u + (unsigned)i)
                                - __nv_logf(tt);
                if (s > best) { best = s; bi = r * 8 + i; }
            }
        }
    }

    const float esum = (es0 + es1) + (es2 + es3);

    // Selected grid value via one cached load
    const float sel = __ldg(base + (size_t)(bi >> 3) * 2048u + (unsigned)(bi & 7));

    const float u = u01f(bbits);

    // Fast f32 sigmoid; double path only inside the 2e-3 boundary band.
    const float e    = __expf(-fabsf(sel));
    const float rr   = __fdividef(1.0f, 1.0f + e);
    const float sigf = (sel >= 0.0f) ? rr : 1.0f - rr;
    const float du   = u - sigf;
    bool acc;
    if (fabsf(du) > 2e-3f) {
        acc = du < 0.0f;
    } else {
        const double sig = 1.0 / (1.0 + exp(-(double)sel));
        acc = u < (float)sig;
    }

    const float lse     = log1pf(e);
    const float bern_lp = (acc ? fminf(sel, 0.0f) : fminf(-sel, 0.0f)) - lse;
    const float cat_lp  = sel - __logf(esum);   // abs err ~2e-6, tol 1e-3

    const int ddi = bi >> 3, ddj = bi & 7;

    // tuple layout: kp_xy [2*524288] | log_probs [524288] | mask [524288]
    ((float2*)out)[w]  = make_float2((float)(wc * 8u + (unsigned)ddj),   // x
                                     (float)(hc * 8u + (unsigned)ddi)); // y
    out[1048576u + w]  = cat_lp + bern_lp;
    out[1572864u + w]  = acc ? 1.0f : 0.0f;
}

extern "C" void kernel_launch(void* const* d_in, const int* in_sizes, int n_in,
                              void* d_out, int out_size) {
    const float* x = (const float*)d_in[0];
    float* out = (float*)d_out;
    keypoint_sampler_kernel<<<8192, 64>>>(x, out);
}

// round 14
// speedup vs baseline: 1.2095x; 1.2095x over previous
#include <cuda_runtime.h>
#include <cstdint>
#include <math.h>

// Accurate libdevice log — used ONLY in the rare exact-fallback path so the
// argmax ordering is provably identical to the XLA reference.
extern "C" __device__ float __nv_logf(float);

// ---------------------------------------------------------------------------
// Compile-time Threefry-2x32 for split keys (partitionable fold-like split).
// ---------------------------------------------------------------------------
constexpr unsigned crotl(unsigned x, int r) { return (x << r) | (x >> (32 - r)); }
struct CKeys { unsigned a, b; };
constexpr CKeys ctf(unsigned k0, unsigned k1, unsigned x0, unsigned x1) {
    unsigned k2 = k0 ^ k1 ^ 0x1BD11BDAu;
    const int rotA[4] = {13, 15, 26, 6};
    const int rotB[4] = {17, 29, 16, 24};
    x0 += k0; x1 += k1;
    for (int i = 0; i < 4; i++) { x0 += x1; x1 = crotl(x1, rotA[i]); x1 ^= x0; }
    x0 += k1; x1 += k2 + 1u;
    for (int i = 0; i < 4; i++) { x0 += x1; x1 = crotl(x1, rotB[i]); x1 ^= x0; }
    x0 += k2; x1 += k0 + 2u;
    for (int i = 0; i < 4; i++) { x0 += x1; x1 = crotl(x1, rotA[i]); x1 ^= x0; }
    x0 += k0; x1 += k1 + 3u;
    for (int i = 0; i < 4; i++) { x0 += x1; x1 = crotl(x1, rotB[i]); x1 ^= x0; }
    x0 += k1; x1 += k2 + 4u;
    for (int i = 0; i < 4; i++) { x0 += x1; x1 = crotl(x1, rotA[i]); x1 ^= x0; }
    x0 += k2; x1 += k0 + 5u;
    return {x0, x1};
}
constexpr CKeys KCAT  = ctf(0u, 42u, 0u, 0u);   // k_cat
constexpr CKeys KBERN = ctf(0u, 42u, 0u, 1u);   // k_bern

// ---------------------------------------------------------------------------
// Device Threefry-2x32; partitionable 32-bit bits = lane0 ^ lane1, ctr (0, j).
// x1 must be ctr + k1 (pre-added by the caller). Plain SHF rotates — the
// proven-fastest form (IMAD/IMAD.WIDE migrations all regressed: R8/R9/R13).
// ---------------------------------------------------------------------------
__device__ __forceinline__ unsigned rotl(unsigned x, int r) {
    return __funnelshift_l(x, x, r);
}

__device__ __forceinline__ unsigned tf_bits32p(unsigned k0, unsigned k1, unsigned x1) {
    const unsigned k2 = k0 ^ k1 ^ 0x1BD11BDAu;
    unsigned x0 = k0;
#define TFR(r) { x0 += x1; x1 = rotl(x1, r); x1 ^= x0; }
    TFR(13) TFR(15) TFR(26) TFR(6)
    x0 += k1; x1 += k2 + 1u;
    TFR(17) TFR(29) TFR(16) TFR(24)
    x0 += k2; x1 += k0 + 2u;
    TFR(13) TFR(15) TFR(26) TFR(6)
    x0 += k0; x1 += k1 + 3u;
    TFR(17) TFR(29) TFR(16) TFR(24)
    x0 += k1; x1 += k2 + 4u;
    TFR(13) TFR(15) TFR(26) TFR(6)
#undef TFR
    return (x0 + k2) ^ (x1 + k0 + 5u);
}

// JAX uniform [0,1): bit-identical to bitcast((bits>>9)|0x3f800000)-1
// ((bits>>9) < 2^23 => exact I2F; *2^-23 exact)
__device__ __forceinline__ float u01f(unsigned bits) {
    return (float)(bits >> 9) * 1.1920928955078125e-7f;   // 2^-23
}

#define TINY    1.17549435e-38f
#define L2E     1.44269504088896340736f   /* 1/ln2 */
#define L2EH    0.72134752044448170368f   /* 1/(2 ln2) */
#define D_SER   0.001953125f              /* d <= 2^-9: use series for -lg2(u) */
#define GAPTHR2 7.5e-4f                   /* s2-units; >=2x worst screen error */

// (value, index) max with exact second-max propagation; ties -> a (lower idx)
struct TopK { float v1; float v2; int i1; };
__device__ __forceinline__ TopK tk_merge(TopK a, TopK b) {
    TopK r;
    if (b.v1 > a.v1) { r.v1 = b.v1; r.i1 = b.i1; r.v2 = fmaxf(a.v1, b.v2); }
    else             { r.v1 = a.v1; r.i1 = a.i1; r.v2 = fmaxf(b.v1, a.v2); }
    return r;
}

// ---------------------------------------------------------------------------
// TWO threads per 8x8 window: even lane rows 0-3 (slots 0-31), odd lane rows
// 4-7 (slots 32-63). Identical proven R12 inner body per 8-slot row; cross-
// lane merge via 4 shuffles (tie -> lower slot index = even lane). Both lanes
// run the epilogue (identical values); even lane stores.
// ---------------------------------------------------------------------------
__global__ __launch_bounds__(128)
void keypoint_sampler_kernel(const float* __restrict__ x, float* __restrict__ out) {
    const unsigned tid  = blockIdx.x * 128u + threadIdx.x;  // 0 .. 1048575
    const unsigned w    = tid >> 1;                         // 0 .. 524287
    const unsigned half = tid & 1u;                         // 0: slots 0-31, 1: 32-63

    const unsigned b  = w >> 16;
    const unsigned hc = (w >> 8) & 255u;
    const unsigned wc = w & 255u;

    const float* base = x + ((size_t)b << 22) + (size_t)(hc * 8u) * 2048u + wc * 8u;

    // Bernoulli bits (counter = w, identical for both lanes of the pair)
    const unsigned bbits = tf_bits32p(KBERN.a, KBERN.b, w + KBERN.b);

    TopK top; top.v1 = -3.4e38f; top.v2 = -3.4e38f; top.i1 = 0;
    float es0 = 0.f, es1 = 0.f;

    const unsigned kbase = half * 32u;            // first slot of my half
    const unsigned cbase = w * 64u;

#pragma unroll 1
    for (int rr = 0; rr < 4; rr++) {
        const unsigned row = half * 4u + (unsigned)rr;          // 0..7
        const float4 p0 = *(const float4*)(base + (size_t)row * 2048u);
        const float4 p1 = *(const float4*)(base + (size_t)row * 2048u + 4u);
        float v[8] = {p0.x, p0.y, p0.z, p0.w, p1.x, p1.y, p1.z, p1.w};

        const unsigned k0s = kbase + (unsigned)rr * 8u;         // slot base
        const unsigned ckr = cbase + k0s + KCAT.b;              // ctr + k1

        // Phase 1: 8 independent threefry chains in flight
        unsigned g[8];
#pragma unroll
        for (int i = 0; i < 8; i++)
            g[i] = tf_bits32p(KCAT.a, KCAT.b, ckr + (unsigned)i);

        // Phase 2: 8 independent score pipelines, branch-free
        float s[8];
#pragma unroll
        for (int i = 0; i < 8; i++) {
            const float u = u01f(g[i]);
            const float d   = 1.0f - u;
            const float t2m = -__log2f(u);                    // MUFU (+inf at u=0)
            const float t2f = d * fmaf(d, L2EH, L2E);         // series path
            const float t2  = (d < D_SER) ? t2f : t2m;
            const float p   = v[i] * L2E;
            s[i] = p - __log2f(t2);                           // score/ln2
            const float ev = exp2f(p);                        // == expf(v)
            if (i & 1) es1 += ev; else es0 += ev;
        }

        // Tournament top-2 within the row (depth 3), ties -> lower index
        TopK t01, t23, t45, t67, ta, tb, row2;
        t01.v1 = (s[1] > s[0]) ? s[1] : s[0];
        t01.i1 = (int)k0s + ((s[1] > s[0]) ? 1 : 0);
        t01.v2 = fminf(s[0], s[1]);
        t23.v1 = (s[3] > s[2]) ? s[3] : s[2];
        t23.i1 = (int)k0s + ((s[3] > s[2]) ? 3 : 2);
        t23.v2 = fminf(s[2], s[3]);
        t45.v1 = (s[5] > s[4]) ? s[5] : s[4];
        t45.i1 = (int)k0s + ((s[5] > s[4]) ? 5 : 4);
        t45.v2 = fminf(s[4], s[5]);
        t67.v1 = (s[7] > s[6]) ? s[7] : s[6];
        t67.i1 = (int)k0s + ((s[7] > s[6]) ? 7 : 6);
        t67.v2 = fminf(s[6], s[7]);
        ta   = tk_merge(t01, t23);
        tb   = tk_merge(t45, t67);
        row2 = tk_merge(ta, tb);
        top  = tk_merge(top, row2);
    }

    // ---- cross-lane merge (pair = lanes 2j, 2j+1) -------------------------
    TopK oth;
    oth.v1 = __shfl_xor_sync(0xFFFFFFFFu, top.v1, 1);
    oth.v2 = __shfl_xor_sync(0xFFFFFFFFu, top.v2, 1);
    oth.i1 = __shfl_xor_sync(0xFFFFFFFFu, top.i1, 1);
    const TopK lo = half ? oth : top;    // lower slot indices
    const TopK hi = half ? top : oth;
    TopK m = tk_merge(lo, hi);           // ties -> lower index (exact ref order)

    float esum = es0 + es1;
    esum += __shfl_xor_sync(0xFFFFFFFFu, esum, 1);

    int bi = m.i1;

    // Ambiguous top-2 (P ~ 1e-3): both lanes redo THEIR OWN half exactly,
    // then re-merge. Uniform across the pair (same m values) -> no divergence.
    if (m.v1 - m.v2 < GAPTHR2) {
        float bestE = -3.4e38f; int biE = (int)kbase;
#pragma unroll 1
        for (int rr = 0; rr < 4; rr++) {
            const unsigned row = half * 4u + (unsigned)rr;
#pragma unroll 1
            for (int i = 0; i < 8; i++) {
                const unsigned k = kbase + (unsigned)rr * 8u + (unsigned)i;
                const unsigned gb = tf_bits32p(KCAT.a, KCAT.b, cbase + k + KCAT.b);
                const float uu = fmaxf(u01f(gb), TINY);
                const float tt = -__nv_logf(uu);
                const float s = __ldg(base + (size_t)row * 2048u + (unsigned)i)
                                - __nv_logf(tt);
                if (s > bestE) { bestE = s; biE = (int)k; }
            }
        }
        const float ob = __shfl_xor_sync(0xFFFFFFFFu, bestE, 1);
        const int   oi = __shfl_xor_sync(0xFFFFFFFFu, biE, 1);
        // lower half wins ties: even lane keeps self unless other strictly >;
        // odd lane yields unless self strictly >.
        const bool otherWins = half ? !(bestE > ob) : (ob > bestE);
        bi = otherWins ? oi : biE;
    }

    // Selected grid value (same address on both lanes -> broadcast load)
    const float sel = __ldg(base + (size_t)(bi >> 3) * 2048u + (unsigned)(bi & 7));

    const float u = u01f(bbits);

    // Fast f32 sigmoid; double path only inside the 2e-3 boundary band.
    const float e    = __expf(-fabsf(sel));
    const float rr2  = __fdividef(1.0f, 1.0f + e);
    const float sigf = (sel >= 0.0f) ? rr2 : 1.0f - rr2;
    const float du   = u - sigf;
    bool acc;
    if (fabsf(du) > 2e-3f) {
        acc = du < 0.0f;
    } else {
        const double sig = 1.0 / (1.0 + exp(-(double)sel));
        acc = u < (float)sig;
    }

    const float lse     = log1pf(e);
    const float bern_lp = (acc ? fminf(sel, 0.0f) : fminf(-sel, 0.0f)) - lse;
    const float cat_lp  = sel - __logf(esum);   // abs err ~2e-6, tol 1e-3

    const int ddi = bi >> 3, ddj = bi & 7;

    // Even lane stores the pair's window (coalesced across the half-warp).
    if (half == 0u) {
        ((float2*)out)[w]  = make_float2((float)(wc * 8u + (unsigned)ddj),   // x
                                         (float)(hc * 8u + (unsigned)ddi)); // y
        out[1048576u + w]  = cat_lp + bern_lp;
        out[1572864u + w]  = acc ? 1.0f : 0.0f;
    }
}

extern "C" void kernel_launch(void* const* d_in, const int* in_sizes, int n_in,
                              void* d_out, int out_size) {
    const float* x = (const float*)d_in[0];
    float* out = (float*)d_out;
    // 2 threads per window: 1,048,576 threads
    keypoint_sampler_kernel<<<8192, 128>>>(x, out);
}